// round 5
// baseline (speedup 1.0000x reference)
#include <cuda_runtime.h>
#include <math.h>

#define TT 512
#define BB 32
#define VV 1296
#define LL 64
#define NROWS (TT*BB)
#define JP (TT/2)      // column pairs per batch
#define RING 8

// Scratch (no allocations allowed anywhere).
// g_pb4[b][jp][l] = {pb[2l][2jp], pb[2l+1][2jp], pb[2l][2jp+1], pb[2l+1][2jp+1]}
__device__ float4        g_pb4[(size_t)BB * JP * 32];
__device__ float4        g_stats[NROWS];        // {se, lse_p, V*lse_p - sum_q, 0}
__device__ int           g_targets[NROWS];
__device__ double        g_sum;
__device__ unsigned int  g_ticket;

// ---------------------------------------------------------------------------
// Fused 3-value block sum-reduction (256 threads). Results valid on tid 0.
// ---------------------------------------------------------------------------
__device__ __forceinline__ void blk_red3(float& a, float& b, float& c)
{
    #pragma unroll
    for (int o = 16; o; o >>= 1) {
        a += __shfl_xor_sync(0xffffffffu, a, o);
        b += __shfl_xor_sync(0xffffffffu, b, o);
        c += __shfl_xor_sync(0xffffffffu, c, o);
    }
    __shared__ float sred[24];
    const int w = threadIdx.x >> 5, l = threadIdx.x & 31;
    if (l == 0) { sred[w] = a; sred[w + 8] = b; sred[w + 16] = c; }
    __syncthreads();
    if (threadIdx.x < 8) {
        a = sred[threadIdx.x];
        b = sred[threadIdx.x + 8];
        c = sred[threadIdx.x + 16];
        #pragma unroll
        for (int o = 4; o; o >>= 1) {
            a += __shfl_xor_sync(0xffu, a, o);
            b += __shfl_xor_sync(0xffu, b, o);
            c += __shfl_xor_sync(0xffu, c, o);
        }
    }
}

// ---------------------------------------------------------------------------
// K1: fused per-row softmax stats + band gather. One block per (t,b) row.
// The gather for column j=t, batch b reads seq_pred[j,b,label[i]] — the very
// row this block is streaming, so those 64 loads are L1 hits.
// Raw values into g_pb4: the per-column log-softmax constant shifts all
// dp[.,j] equally, so the DP's strict comparisons are unchanged.
// Stores per row: se = sum(exp(s)), lse_p = log(sum(exp(q))),
//                 D = V*lse_p - sum(q).
// ---------------------------------------------------------------------------
__global__ void __launch_bounds__(256) stats_gather_kernel(
    const float* __restrict__ pred,
    const float* __restrict__ seq_pred,
    const int*   __restrict__ label,
    const int*   __restrict__ x_len,
    const int*   __restrict__ label_len)
{
    const int row = blockIdx.x;              // row = t*BB + b (contiguous)
    const int b   = row & (BB - 1);
    const int t   = row >> 5;
    const int tid = threadIdx.x;

    if (row == 0 && tid == 0) { g_sum = 0.0; g_ticket = 0u; }

    const int C = __ldg(&x_len[b]);
    if (t >= C) return;                      // masked row: skip 10KB read

    const size_t base = (size_t)row * VV;
    const float4* __restrict__ sp4 = (const float4*)(seq_pred + base);
    const float4* __restrict__ p4  = (const float4*)(pred + base);
    const bool has2 = tid < (VV / 4 - 256);  // 324 float4s per row

    const float4 s0 = sp4[tid];
    const float4 q0 = p4[tid];
    float4 s1, q1;
    if (has2) { s1 = sp4[tid + 256]; q1 = p4[tid + 256]; }

    // Band gather (threads 0..63): L1-hot scalar loads from this same row.
    if (tid < LL) {
        const int i = tid;
        const int R = __ldg(&label_len[b]);
        float v = __int_as_float(0xff800000);
        if (i < R && t >= i && t <= C - R + i) {
            const int lab = __ldg(&label[b * LL + i]);
            v = __ldg(&seq_pred[base + lab]);
        }
        ((float*)g_pb4)[(((size_t)b * JP + (t >> 1)) * 32 + (i >> 1)) * 4
                        + ((t & 1) * 2 + (i & 1))] = v;
    }

    float se = __expf(s0.x) + __expf(s0.y) + __expf(s0.z) + __expf(s0.w);
    float pe = __expf(q0.x) + __expf(q0.y) + __expf(q0.z) + __expf(q0.w);
    float sl = q0.x + q0.y + q0.z + q0.w;
    if (has2) {
        se += __expf(s1.x) + __expf(s1.y) + __expf(s1.z) + __expf(s1.w);
        pe += __expf(q1.x) + __expf(q1.y) + __expf(q1.z) + __expf(q1.w);
        sl += q1.x + q1.y + q1.z + q1.w;
    }

    blk_red3(se, pe, sl);

    if (tid == 0) {
        const float lse_p = __logf(pe);
        g_stats[row] = make_float4(se, lse_p, (float)VV * lse_p - sl, 0.0f);
    }
}

// ---------------------------------------------------------------------------
// K2: per-batch DP scan + backtrack. 1 warp per batch, lane l owns rows
// 2l,2l+1. Two time-columns per shuffle round, RING-deep float4 prefetch
// over the L2-resident packed band.
// ---------------------------------------------------------------------------
__global__ void __launch_bounds__(32) dp_kernel(
    const int* __restrict__ label,
    const int* __restrict__ x_len,
    const int* __restrict__ label_len)
{
    __shared__ unsigned long long ch[TT];    // per-column choice ballots
    __shared__ int labs[LL];

    const int b = blockIdx.x;
    const int l = threadIdx.x;
    const int C = x_len[b];
    const int R = label_len[b];
    const float ninf = __int_as_float(0xff800000);

    labs[l]      = label[b * LL + l];
    labs[l + 32] = label[b * LL + l + 32];
    if (l == 0) ch[0] = 0ULL;

    const float4* __restrict__ pb = g_pb4 + (size_t)b * JP * 32;

    const int jlast = C - 1;                 // C >= 256 always
    const int jpmax = jlast >> 1;

    // jp = 0: column 0 init (.x), column 1 single step (.z/.w)
    const float4 f0 = pb[l];
    float dlo = (l == 0) ? f0.x : ninf;
    float dhi = ninf;
    {
        float ph = __shfl_up_sync(0xffffffffu, dhi, 1);
        if (l == 0) ph = ninf;
        const bool clo = ph > dlo, chi_ = dlo > dhi;   // strict, as reference
        const unsigned blo = __ballot_sync(0xffffffffu, clo);
        const unsigned bhi = __ballot_sync(0xffffffffu, chi_);
        const float nlo = fmaxf(ph, dlo) + f0.z;
        const float nhi = fmaxf(dlo, dhi) + f0.w;
        if (l == 0) ch[1] = (unsigned long long)blo | ((unsigned long long)bhi << 32);
        dlo = nlo; dhi = nhi;
    }

    float4 buf[RING];
    #pragma unroll
    for (int k = 0; k < RING; ++k) {
        int jp = 1 + k; if (jp > jpmax) jp = jpmax;
        buf[k] = pb[jp * 32 + l];
    }

    int jp = 1, k = 0;
    while (2 * jp + 1 <= jlast) {
        const float4 f = buf[k];
        int njp = jp + RING; if (njp > jpmax) njp = jpmax;
        buf[k] = pb[njp * 32 + l];           // prefetch (clamped dup ok)
        k = (k + 1) & (RING - 1);

        // Off-chain shuffles: pm1 = pb[2l-1][2jp]; plo/phi = dp rows 2l-2,2l-1
        float pm1 = __shfl_up_sync(0xffffffffu, f.y, 1);
        float plo = __shfl_up_sync(0xffffffffu, dlo, 1);
        float phi = __shfl_up_sync(0xffffffffu, dhi, 1);
        if (l == 0) { pm1 = ninf; plo = ninf; phi = ninf; }

        const int j = 2 * jp;
        // column j (row 2l-1 recomputed; its choice bit comes from lane l-1's c1)
        const float a_m1 = fmaxf(plo, phi) + pm1;
        const bool  c0   = phi > dlo;  const float a0 = fmaxf(phi, dlo) + f.x;
        const bool  c1   = dlo > dhi;  const float a1 = fmaxf(dlo, dhi) + f.y;
        // column j+1 (all operands lane-local)
        const bool  c0p  = a_m1 > a0;  const float nlo = fmaxf(a_m1, a0) + f.z;
        const bool  c1p  = a0   > a1;  const float nhi = fmaxf(a0,   a1) + f.w;

        const unsigned b0 = __ballot_sync(0xffffffffu, c0);
        const unsigned b1 = __ballot_sync(0xffffffffu, c1);
        const unsigned b2 = __ballot_sync(0xffffffffu, c0p);
        const unsigned b3 = __ballot_sync(0xffffffffu, c1p);
        if (l == 0) {
            ch[j]     = (unsigned long long)b0 | ((unsigned long long)b1 << 32);
            ch[j + 1] = (unsigned long long)b2 | ((unsigned long long)b3 << 32);
        }
        dlo = nlo; dhi = nhi;
        ++jp;
    }

    if (2 * jp == jlast) {                   // even tail column
        float ph = __shfl_up_sync(0xffffffffu, dhi, 1);
        if (l == 0) ph = ninf;
        const bool clo = ph > dlo, chi_ = dlo > dhi;
        const unsigned blo = __ballot_sync(0xffffffffu, clo);
        const unsigned bhi = __ballot_sync(0xffffffffu, chi_);
        if (l == 0) ch[jlast] = (unsigned long long)blo | ((unsigned long long)bhi << 32);
    }
    __syncwarp();

    // Serial backtrack (targets only needed for active columns j < C):
    // ch loads are row-independent; dependent chain is shift+and+sub only.
    if (l == 0) {
        int row = R - 1;
        #pragma unroll 4
        for (int jj = C - 1; jj >= 0; --jj) {
            g_targets[jj * BB + b] = labs[row];
            const unsigned long long w = ch[jj];
            const int sh = ((row & 1) << 5) | (row >> 1);
            row -= (int)((w >> sh) & 1ULL);
        }
    }
}

// ---------------------------------------------------------------------------
// K3: per-row CE correction + grid reduction. One thread per row; two
// scattered scalar loads per active row (high MLP across 16K threads).
// Last block (ticket) writes the mean — no separate epilogue kernel.
//   ce = smooth*D - (conf - smooth)*(p_t - lse_p),  conf = exp(sp_t)/se
// ---------------------------------------------------------------------------
__global__ void __launch_bounds__(256) finalize_kernel(
    const float* __restrict__ pred,
    const float* __restrict__ seq_pred,
    const int*   __restrict__ x_len,
    float*       __restrict__ out)
{
    const int row = blockIdx.x * 256 + threadIdx.x;
    const int b   = row & (BB - 1);
    const int t   = row >> 5;

    float ce = 0.0f;
    if (t < __ldg(&x_len[b])) {
        const float4 st  = g_stats[row];
        const int    tgt = g_targets[row];
        const size_t base = (size_t)row * VV;
        const float sp_t = __ldg(&seq_pred[base + tgt]);
        const float p_t  = __ldg(&pred[base + tgt]);
        const float conf   = __expf(sp_t) / st.x;
        const float smooth = (1.0f - conf) * (1.0f / (float)(VV - 1));
        ce = smooth * st.z - (conf - smooth) * (p_t - st.y);
    }

    // Block reduce (double)
    double s = (double)ce;
    #pragma unroll
    for (int o = 16; o; o >>= 1)
        s += __shfl_xor_sync(0xffffffffu, s, o);
    __shared__ double sm[8];
    const int w = threadIdx.x >> 5, l = threadIdx.x & 31;
    if (l == 0) sm[w] = s;
    __syncthreads();
    if (threadIdx.x == 0) {
        double x = sm[0] + sm[1] + sm[2] + sm[3] + sm[4] + sm[5] + sm[6] + sm[7];
        atomicAdd(&g_sum, x);
        __threadfence();
        const unsigned tk = atomicAdd(&g_ticket, 1u);
        if (tk == gridDim.x - 1) {
            const double total = atomicAdd(&g_sum, 0.0);   // all adds visible
            out[0] = (float)(total / (double)NROWS);
        }
    }
}

// ---------------------------------------------------------------------------
extern "C" void kernel_launch(void* const* d_in, const int* in_sizes, int n_in,
                              void* d_out, int out_size)
{
    const float* pred      = (const float*)d_in[0];
    const float* seq_pred  = (const float*)d_in[1];
    const int*   label     = (const int*)d_in[2];
    const int*   x_len     = (const int*)d_in[3];
    const int*   label_len = (const int*)d_in[4];

    stats_gather_kernel<<<NROWS, 256>>>(pred, seq_pred, label, x_len, label_len);
    dp_kernel<<<BB, 32>>>(label, x_len, label_len);
    finalize_kernel<<<NROWS / 256, 256>>>(pred, seq_pred, x_len, (float*)d_out);
}